// round 6
// baseline (speedup 1.0000x reference)
#include <cuda_runtime.h>
#include <math.h>

#define NN 65536
#define EE 524288
#define DHH 64
#define HH 4
#define DDIM 16

// ---------------- device scratch (no allocations allowed) ----------------
__device__ float g_q[NN * DHH];
__device__ float g_k[NN * DHH];
__device__ float g_v[NN * DHH];
__device__ float g_e[(size_t)EE * DHH];   // edge projection scratch (128 MiB)
__device__ float g_w[EE * HH];            // scores, then softmax numerators
__device__ unsigned g_smax[NN * HH];      // ordered-encoded float max
__device__ float g_ssum[NN * HH];
__device__ float g_attn[NN * DHH];

// ordered-uint encoding so atomicMax(unsigned) == float max
__device__ __forceinline__ unsigned enc_f(float f) {
    unsigned u = __float_as_uint(f);
    return (u & 0x80000000u) ? ~u : (u | 0x80000000u);
}
__device__ __forceinline__ float dec_f(unsigned k) {
    return (k & 0x80000000u) ? __uint_as_float(k ^ 0x80000000u)
                             : __uint_as_float(~k);
}

// ---------------- init: zero accumulators ----------------
__global__ void k_init() {
    int i = blockIdx.x * blockDim.x + threadIdx.x;
    if (i < NN * HH) { g_smax[i] = 0u; g_ssum[i] = 0.f; }
    if (i < NN * DHH) { g_attn[i] = 0.f; }
}

// ---------------- node LN + QKV projections ----------------
// 64 rows per block, 256 threads, register-tiled 4x4 GEMM per weight.
__global__ void k_node_qkv(const float* __restrict__ x,
                           const float* __restrict__ g1, const float* __restrict__ b1,
                           const float* __restrict__ Wq, const float* __restrict__ bq,
                           const float* __restrict__ Wk, const float* __restrict__ bk,
                           const float* __restrict__ Wv, const float* __restrict__ bv) {
    extern __shared__ float sm[];
    float* xs = sm;             // 64*68
    float* ws = sm + 64 * 68;   // 3*4096
    int tid = threadIdx.x;
    int base = blockIdx.x * 64;

    for (int i = tid; i < 4096; i += 256) {
        xs[(i >> 6) * 68 + (i & 63)] = x[(size_t)base * 64 + i];
        ws[i] = Wq[i];
        ws[4096 + i] = Wk[i];
        ws[8192 + i] = Wv[i];
    }
    __syncthreads();

    // LayerNorm: 4 threads per row
    {
        int row = tid >> 2, qq = tid & 3;
        float s = 0.f, s2 = 0.f;
#pragma unroll
        for (int j = 0; j < 16; j++) {
            float v = xs[row * 68 + qq * 16 + j];
            s += v; s2 += v * v;
        }
        s += __shfl_xor_sync(0xffffffffu, s, 1);
        s2 += __shfl_xor_sync(0xffffffffu, s2, 1);
        s += __shfl_xor_sync(0xffffffffu, s, 2);
        s2 += __shfl_xor_sync(0xffffffffu, s2, 2);
        float m = s * (1.f / 64.f);
        float var = s2 * (1.f / 64.f) - m * m;
        float inv = rsqrtf(var + 1e-5f);
#pragma unroll
        for (int j = 0; j < 16; j++) {
            int c = qq * 16 + j;
            xs[row * 68 + c] = (xs[row * 68 + c] - m) * inv * g1[c] + b1[c];
        }
    }
    __syncthreads();

    int ty = tid >> 4, tx = tid & 15;
    int r0 = ty * 4, c0 = tx * 4;
    const float* bias[3] = { bq, bk, bv };
    float* outs[3] = { g_q, g_k, g_v };

    for (int mmat = 0; mmat < 3; mmat++) {
        const float* W = ws + mmat * 4096;
        float acc[4][4] = {};
        for (int k = 0; k < 64; k += 4) {
            float xr[4][4];
#pragma unroll
            for (int i = 0; i < 4; i++) {
                float4 t = *(const float4*)&xs[(r0 + i) * 68 + k];
                xr[i][0] = t.x; xr[i][1] = t.y; xr[i][2] = t.z; xr[i][3] = t.w;
            }
#pragma unroll
            for (int kk = 0; kk < 4; kk++) {
                float4 w = *(const float4*)&W[(k + kk) * 64 + c0];
#pragma unroll
                for (int i = 0; i < 4; i++) {
                    acc[i][0] += xr[i][kk] * w.x;
                    acc[i][1] += xr[i][kk] * w.y;
                    acc[i][2] += xr[i][kk] * w.z;
                    acc[i][3] += xr[i][kk] * w.w;
                }
            }
        }
        const float* bb = bias[mmat];
        float* op = outs[mmat];
#pragma unroll
        for (int i = 0; i < 4; i++) {
            float4 o;
            o.x = acc[i][0] + bb[c0 + 0];
            o.y = acc[i][1] + bb[c0 + 1];
            o.z = acc[i][2] + bb[c0 + 2];
            o.w = acc[i][3] + bb[c0 + 3];
            *(float4*)&op[(size_t)(base + r0 + i) * 64 + c0] = o;
        }
    }
}

// ---------------- edge LN + We projection ----------------
__global__ void k_edge_proj(const float* __restrict__ ea,
                            const float* __restrict__ g1, const float* __restrict__ b1,
                            const float* __restrict__ We, const float* __restrict__ be) {
    extern __shared__ float sm[];
    float* xs = sm;             // 64*68
    float* ws = sm + 64 * 68;   // 4096
    int tid = threadIdx.x;
    int base = blockIdx.x * 64;

    for (int i = tid; i < 4096; i += 256) {
        xs[(i >> 6) * 68 + (i & 63)] = ea[(size_t)base * 64 + i];
        ws[i] = We[i];
    }
    __syncthreads();

    {
        int row = tid >> 2, qq = tid & 3;
        float s = 0.f, s2 = 0.f;
#pragma unroll
        for (int j = 0; j < 16; j++) {
            float v = xs[row * 68 + qq * 16 + j];
            s += v; s2 += v * v;
        }
        s += __shfl_xor_sync(0xffffffffu, s, 1);
        s2 += __shfl_xor_sync(0xffffffffu, s2, 1);
        s += __shfl_xor_sync(0xffffffffu, s, 2);
        s2 += __shfl_xor_sync(0xffffffffu, s2, 2);
        float m = s * (1.f / 64.f);
        float var = s2 * (1.f / 64.f) - m * m;
        float inv = rsqrtf(var + 1e-5f);
#pragma unroll
        for (int j = 0; j < 16; j++) {
            int c = qq * 16 + j;
            xs[row * 68 + c] = (xs[row * 68 + c] - m) * inv * g1[c] + b1[c];
        }
    }
    __syncthreads();

    int ty = tid >> 4, tx = tid & 15;
    int r0 = ty * 4, c0 = tx * 4;
    float acc[4][4] = {};
    for (int k = 0; k < 64; k += 4) {
        float xr[4][4];
#pragma unroll
        for (int i = 0; i < 4; i++) {
            float4 t = *(const float4*)&xs[(r0 + i) * 68 + k];
            xr[i][0] = t.x; xr[i][1] = t.y; xr[i][2] = t.z; xr[i][3] = t.w;
        }
#pragma unroll
        for (int kk = 0; kk < 4; kk++) {
            float4 w = *(const float4*)&ws[(k + kk) * 64 + c0];
#pragma unroll
            for (int i = 0; i < 4; i++) {
                acc[i][0] += xr[i][kk] * w.x;
                acc[i][1] += xr[i][kk] * w.y;
                acc[i][2] += xr[i][kk] * w.z;
                acc[i][3] += xr[i][kk] * w.w;
            }
        }
    }
#pragma unroll
    for (int i = 0; i < 4; i++) {
        float4 o;
        o.x = acc[i][0] + be[c0 + 0];
        o.y = acc[i][1] + be[c0 + 1];
        o.z = acc[i][2] + be[c0 + 2];
        o.w = acc[i][3] + be[c0 + 3];
        *(float4*)&g_e[(size_t)(base + r0 + i) * 64 + c0] = o;
    }
}

// ---------------- per-edge scores: rotate K, modulate by e, dot with Q ------
// one warp per edge; lane owns columns lane and lane+32
__global__ void k_score(const int* __restrict__ eidx,
                        const float* __restrict__ edge_w,
                        const float* __restrict__ attn_bi) {
    __shared__ float ew[1024];
    __shared__ float bi[4];
    int tid = threadIdx.x;
    for (int i = tid; i < 1024; i += 256) ew[i] = edge_w[i];
    if (tid < 4) bi[tid] = attn_bi[tid * 2];   // attn_bi[:,0]
    __syncthreads();

    int e = blockIdx.x * 8 + (tid >> 5);
    int lane = tid & 31;
    int src = eidx[e];
    int dst = eidx[EE + e];

    float k0 = g_k[(size_t)src * 64 + lane];
    float k1 = g_k[(size_t)src * 64 + 32 + lane];
    int h0 = lane >> 4, c = lane & 15;

    float kr0 = 0.f, kr1 = 0.f;
#pragma unroll
    for (int d = 0; d < 16; d++) {
        int sl = (h0 << 4) + d;
        float a0 = __shfl_sync(0xffffffffu, k0, sl);
        float a1 = __shfl_sync(0xffffffffu, k1, sl);
        kr0 += a0 * ew[h0 * 256 + d * 16 + c];
        kr1 += a1 * ew[(2 + h0) * 256 + d * 16 + c];
    }
    kr0 *= g_e[(size_t)e * 64 + lane];
    kr1 *= g_e[(size_t)e * 64 + 32 + lane];

    float p0 = g_q[(size_t)dst * 64 + lane] * kr0;
    float p1 = g_q[(size_t)dst * 64 + 32 + lane] * kr1;
#pragma unroll
    for (int m = 1; m < 16; m <<= 1) {
        p0 += __shfl_xor_sync(0xffffffffu, p0, m);
        p1 += __shfl_xor_sync(0xffffffffu, p1, m);
    }
    if ((lane & 15) == 0) {
        const float scale = 0.25f;  // 1/sqrt(16)
        float s0 = p0 * scale + bi[h0];
        float s1 = p1 * scale + bi[2 + h0];
        g_w[e * 4 + h0] = s0;
        g_w[e * 4 + 2 + h0] = s1;
        atomicMax(&g_smax[dst * 4 + h0], enc_f(s0));
        atomicMax(&g_smax[dst * 4 + 2 + h0], enc_f(s1));
    }
}

// ---------------- segment softmax: exp + segment sum ----------------
__global__ void k_norm(const int* __restrict__ eidx) {
    int i = blockIdx.x * blockDim.x + threadIdx.x;   // E*H
    int e = i >> 2, h = i & 3;
    int dst = eidx[EE + e];
    float w = expf(g_w[i] - dec_f(g_smax[dst * 4 + h]));
    g_w[i] = w;
    atomicAdd(&g_ssum[dst * 4 + h], w);
}

// ---------------- rotate V, weight by alpha, scatter-add ----------------
__global__ void k_scatter(const int* __restrict__ eidx,
                          const float* __restrict__ msg_w) {
    __shared__ float mw[1024];
    int tid = threadIdx.x;
    for (int i = tid; i < 1024; i += 256) mw[i] = msg_w[i];
    __syncthreads();

    int e = blockIdx.x * 8 + (tid >> 5);
    int lane = tid & 31;
    int src = eidx[e];
    int dst = eidx[EE + e];

    float v0 = g_v[(size_t)src * 64 + lane];
    float v1 = g_v[(size_t)src * 64 + 32 + lane];
    int h0 = lane >> 4, c = lane & 15;

    float vr0 = 0.f, vr1 = 0.f;
#pragma unroll
    for (int d = 0; d < 16; d++) {
        int sl = (h0 << 4) + d;
        float a0 = __shfl_sync(0xffffffffu, v0, sl);
        float a1 = __shfl_sync(0xffffffffu, v1, sl);
        vr0 += a0 * mw[h0 * 256 + d * 16 + c];
        vr1 += a1 * mw[(2 + h0) * 256 + d * 16 + c];
    }
    float al0 = g_w[e * 4 + h0] / (g_ssum[dst * 4 + h0] + 1e-16f);
    float al1 = g_w[e * 4 + 2 + h0] / (g_ssum[dst * 4 + 2 + h0] + 1e-16f);
    atomicAdd(&g_attn[(size_t)dst * 64 + lane], al0 * vr0);
    atomicAdd(&g_attn[(size_t)dst * 64 + 32 + lane], al1 * vr1);
}

// ---------------- epilogue: Wo + gated residual + LN + FFN ----------------
// Weights (Wo/W1/W2) are read through __ldg from global: identical across all
// blocks -> resident in L1/L2, freeing smem so 3 CTAs/SM fit (was 1).
__global__ void k_epi(const float* __restrict__ x,
                      const float* __restrict__ Wo, const float* __restrict__ bo,
                      const float* __restrict__ skip,
                      const float* __restrict__ g2, const float* __restrict__ b2,
                      const float* __restrict__ W1, const float* __restrict__ b1f,
                      const float* __restrict__ W2, const float* __restrict__ b2f,
                      float* __restrict__ out) {
    extern __shared__ float sm[];
    float* s_a  = sm;               // 64*68 = 4352 (attn tile, later hn2)
    float* s_h  = s_a + 4352;       // 4352
    float* s_u  = s_h + 4352;       // 64*132 = 8448

    int tid = threadIdx.x;
    int base = blockIdx.x * 64;

    for (int i = tid; i < 4096; i += 256) {
        s_a[(i >> 6) * 68 + (i & 63)] = g_attn[(size_t)base * 64 + i];
    }
    __syncthreads();

    int ty = tid >> 4, tx = tid & 15;
    int r0 = ty * 4, c0 = tx * 4;
    float gsig = 1.f / (1.f + expf(-skip[0]));
    float hreg[4][4];

    // stage 1: o = attn @ Wo + bo ; h = g*o + (1-g)*x
    {
        float acc[4][4] = {};
        for (int k = 0; k < 64; k += 4) {
            float xr[4][4];
#pragma unroll
            for (int i = 0; i < 4; i++) {
                float4 t = *(const float4*)&s_a[(r0 + i) * 68 + k];
                xr[i][0] = t.x; xr[i][1] = t.y; xr[i][2] = t.z; xr[i][3] = t.w;
            }
#pragma unroll
            for (int kk = 0; kk < 4; kk++) {
                float4 w = __ldg((const float4*)&Wo[(k + kk) * 64 + c0]);
#pragma unroll
                for (int i = 0; i < 4; i++) {
                    acc[i][0] += xr[i][kk] * w.x;
                    acc[i][1] += xr[i][kk] * w.y;
                    acc[i][2] += xr[i][kk] * w.z;
                    acc[i][3] += xr[i][kk] * w.w;
                }
            }
        }
#pragma unroll
        for (int i = 0; i < 4; i++) {
            float4 xv = *(const float4*)&x[(size_t)(base + r0 + i) * 64 + c0];
            hreg[i][0] = gsig * (acc[i][0] + bo[c0 + 0]) + (1.f - gsig) * xv.x;
            hreg[i][1] = gsig * (acc[i][1] + bo[c0 + 1]) + (1.f - gsig) * xv.y;
            hreg[i][2] = gsig * (acc[i][2] + bo[c0 + 2]) + (1.f - gsig) * xv.z;
            hreg[i][3] = gsig * (acc[i][3] + bo[c0 + 3]) + (1.f - gsig) * xv.w;
            float4 hv;
            hv.x = hreg[i][0]; hv.y = hreg[i][1]; hv.z = hreg[i][2]; hv.w = hreg[i][3];
            *(float4*)&s_h[(r0 + i) * 68 + c0] = hv;
        }
    }
    __syncthreads();

    // stage 2: hn2 = LN(h) -> s_a
    {
        int row = tid >> 2, qq = tid & 3;
        float s = 0.f, s2 = 0.f;
#pragma unroll
        for (int j = 0; j < 16; j++) {
            float v = s_h[row * 68 + qq * 16 + j];
            s += v; s2 += v * v;
        }
        s += __shfl_xor_sync(0xffffffffu, s, 1);
        s2 += __shfl_xor_sync(0xffffffffu, s2, 1);
        s += __shfl_xor_sync(0xffffffffu, s, 2);
        s2 += __shfl_xor_sync(0xffffffffu, s2, 2);
        float m = s * (1.f / 64.f);
        float var = s2 * (1.f / 64.f) - m * m;
        float inv = rsqrtf(var + 1e-5f);
#pragma unroll
        for (int j = 0; j < 16; j++) {
            int cc = qq * 16 + j;
            s_a[row * 68 + cc] = (s_h[row * 68 + cc] - m) * inv * g2[cc] + b2[cc];
        }
    }
    __syncthreads();

    // stage 3: u = relu(hn2 @ W1 + b1) -> s_u (64x128)
    {
        float acc[4][8] = {};
        for (int k = 0; k < 64; k += 4) {
            float xr[4][4];
#pragma unroll
            for (int i = 0; i < 4; i++) {
                float4 t = *(const float4*)&s_a[(r0 + i) * 68 + k];
                xr[i][0] = t.x; xr[i][1] = t.y; xr[i][2] = t.z; xr[i][3] = t.w;
            }
#pragma unroll
            for (int kk = 0; kk < 4; kk++) {
                float4 wa = __ldg((const float4*)&W1[(k + kk) * 128 + tx * 8]);
                float4 wb = __ldg((const float4*)&W1[(k + kk) * 128 + tx * 8 + 4]);
#pragma unroll
                for (int i = 0; i < 4; i++) {
                    acc[i][0] += xr[i][kk] * wa.x;
                    acc[i][1] += xr[i][kk] * wa.y;
                    acc[i][2] += xr[i][kk] * wa.z;
                    acc[i][3] += xr[i][kk] * wa.w;
                    acc[i][4] += xr[i][kk] * wb.x;
                    acc[i][5] += xr[i][kk] * wb.y;
                    acc[i][6] += xr[i][kk] * wb.z;
                    acc[i][7] += xr[i][kk] * wb.w;
                }
            }
        }
        int u0 = tx * 8;
#pragma unroll
        for (int i = 0; i < 4; i++) {
#pragma unroll
            for (int j = 0; j < 8; j++) {
                float uu = acc[i][j] + b1f[u0 + j];
                s_u[(r0 + i) * 132 + u0 + j] = fmaxf(uu, 0.f);
            }
        }
    }
    __syncthreads();

    // stage 4: out = h + u @ W2 + b2
    {
        float acc[4][4] = {};
        for (int k = 0; k < 128; k += 4) {
            float xr[4][4];
#pragma unroll
            for (int i = 0; i < 4; i++) {
                float4 t = *(const float4*)&s_u[(r0 + i) * 132 + k];
                xr[i][0] = t.x; xr[i][1] = t.y; xr[i][2] = t.z; xr[i][3] = t.w;
            }
#pragma unroll
            for (int kk = 0; kk < 4; kk++) {
                float4 w = __ldg((const float4*)&W2[(k + kk) * 64 + c0]);
#pragma unroll
                for (int i = 0; i < 4; i++) {
                    acc[i][0] += xr[i][kk] * w.x;
                    acc[i][1] += xr[i][kk] * w.y;
                    acc[i][2] += xr[i][kk] * w.z;
                    acc[i][3] += xr[i][kk] * w.w;
                }
            }
        }
#pragma unroll
        for (int i = 0; i < 4; i++) {
            float4 o;
            o.x = hreg[i][0] + acc[i][0] + b2f[c0 + 0];
            o.y = hreg[i][1] + acc[i][1] + b2f[c0 + 1];
            o.z = hreg[i][2] + acc[i][2] + b2f[c0 + 2];
            o.w = hreg[i][3] + acc[i][3] + b2f[c0 + 3];
            *(float4*)&out[(size_t)(base + r0 + i) * 64 + c0] = o;
        }
    }
}

// ---------------- host launcher ----------------
extern "C" void kernel_launch(void* const* d_in, const int* in_sizes, int n_in,
                              void* d_out, int out_size) {
    const float* x      = (const float*)d_in[0];
    const int*   eidx   = (const int*)d_in[1];
    const float* ea     = (const float*)d_in[2];
    const float* Wq     = (const float*)d_in[3];
    const float* bq     = (const float*)d_in[4];
    const float* Wk     = (const float*)d_in[5];
    const float* bk     = (const float*)d_in[6];
    const float* Wv     = (const float*)d_in[7];
    const float* bv     = (const float*)d_in[8];
    const float* We     = (const float*)d_in[9];
    const float* be     = (const float*)d_in[10];
    const float* Wo     = (const float*)d_in[11];
    const float* bo     = (const float*)d_in[12];
    const float* edge_w = (const float*)d_in[13];
    const float* msg_w  = (const float*)d_in[14];
    const float* skip   = (const float*)d_in[15];
    const float* ln1_g  = (const float*)d_in[16];
    const float* ln1_b  = (const float*)d_in[17];
    const float* lne_g  = (const float*)d_in[18];
    const float* lne_b  = (const float*)d_in[19];
    const float* ln2_g  = (const float*)d_in[20];
    const float* ln2_b  = (const float*)d_in[21];
    const float* W1     = (const float*)d_in[22];
    const float* b1     = (const float*)d_in[23];
    const float* W2     = (const float*)d_in[24];
    const float* b2     = (const float*)d_in[25];
    const float* attn_bi= (const float*)d_in[26];
    float* out = (float*)d_out;

    // opt-in to >48KB dynamic smem (idempotent, cheap; not a stream op)
    cudaFuncSetAttribute(k_node_qkv, cudaFuncAttributeMaxDynamicSharedMemorySize, 67584);
    cudaFuncSetAttribute(k_epi,      cudaFuncAttributeMaxDynamicSharedMemorySize, 69632);

    k_init<<<(NN * DHH + 255) / 256, 256>>>();
    k_node_qkv<<<NN / 64, 256, 66560>>>(x, ln1_g, ln1_b, Wq, bq, Wk, bk, Wv, bv);
    k_edge_proj<<<EE / 64, 256, 33792>>>(ea, lne_g, lne_b, We, be);
    k_score<<<EE / 8, 256>>>(eidx, edge_w, attn_bi);
    k_norm<<<(EE * HH) / 256, 256>>>(eidx);
    k_scatter<<<EE / 8, 256>>>(eidx, msg_w);
    k_epi<<<NN / 64, 256, 68608>>>(x, Wo, bo, skip, ln2_g, ln2_b, W1, b1, W2, b2, out);
}

// round 7
// speedup vs baseline: 1.6360x; 1.6360x over previous
#include <cuda_runtime.h>
#include <math.h>

#define NN 65536
#define EE 524288
#define DHH 64
#define HH 4
#define DDIM 16

// ---------------- device scratch (no allocations allowed) ----------------
__device__ float g_q[NN * DHH];
__device__ float g_k[NN * DHH];   // holds ROTATED k (k @ edge_w per head)
__device__ float g_v[NN * DHH];   // holds ROTATED v (v @ msg_w per head)
__device__ float g_e[(size_t)EE * DHH];
__device__ float g_w[EE * HH];
__device__ unsigned g_smax[NN * HH];
__device__ float g_ssum[NN * HH];
__device__ float g_attn[NN * DHH];

__device__ __forceinline__ unsigned enc_f(float f) {
    unsigned u = __float_as_uint(f);
    return (u & 0x80000000u) ? ~u : (u | 0x80000000u);
}
__device__ __forceinline__ float dec_f(unsigned k) {
    return (k & 0x80000000u) ? __uint_as_float(k ^ 0x80000000u)
                             : __uint_as_float(~k);
}

// ---------------- init ----------------
__global__ void k_init() {
    int i = blockIdx.x * blockDim.x + threadIdx.x;
    if (i < NN * HH) { g_smax[i] = 0u; g_ssum[i] = 0.f; }
    if (i < NN * DHH) { g_attn[i] = 0.f; }
}

// ---------------- node LN + QKV + per-head rotations (hoisted!) -------------
// The reference's per-edge rotations k_j@edge_w / v_j@msg_w depend only on the
// source NODE, so rotate once per node here (8x less work than per-edge).
__global__ void k_node_qkv(const float* __restrict__ x,
                           const float* __restrict__ g1, const float* __restrict__ b1,
                           const float* __restrict__ Wq, const float* __restrict__ bq,
                           const float* __restrict__ Wk, const float* __restrict__ bk,
                           const float* __restrict__ Wv, const float* __restrict__ bv,
                           const float* __restrict__ edge_w,
                           const float* __restrict__ msg_w) {
    extern __shared__ float sm[];
    float* xs = sm;               // 64*68 = 4352
    float* ws = xs + 4352;        // 3*4096 = 12288
    float* kt = ws + 12288;       // 64*68 = 4352
    float* vt = kt + 4352;        // 64*68 = 4352
    float* ew = vt + 4352;        // 1024
    float* mw = ew + 1024;        // 1024   -> total 27392 floats = 109568 B
    int tid = threadIdx.x;
    int base = blockIdx.x * 64;

    for (int i = tid; i < 4096; i += 256) {
        xs[(i >> 6) * 68 + (i & 63)] = x[(size_t)base * 64 + i];
        ws[i] = Wq[i];
        ws[4096 + i] = Wk[i];
        ws[8192 + i] = Wv[i];
    }
    for (int i = tid; i < 1024; i += 256) {
        ew[i] = edge_w[i];
        mw[i] = msg_w[i];
    }
    __syncthreads();

    // LayerNorm: 4 threads per row
    {
        int row = tid >> 2, qq = tid & 3;
        float s = 0.f, s2 = 0.f;
#pragma unroll
        for (int j = 0; j < 16; j++) {
            float v = xs[row * 68 + qq * 16 + j];
            s += v; s2 += v * v;
        }
        s += __shfl_xor_sync(0xffffffffu, s, 1);
        s2 += __shfl_xor_sync(0xffffffffu, s2, 1);
        s += __shfl_xor_sync(0xffffffffu, s, 2);
        s2 += __shfl_xor_sync(0xffffffffu, s2, 2);
        float m = s * (1.f / 64.f);
        float var = s2 * (1.f / 64.f) - m * m;
        float inv = rsqrtf(var + 1e-5f);
#pragma unroll
        for (int j = 0; j < 16; j++) {
            int c = qq * 16 + j;
            xs[row * 68 + c] = (xs[row * 68 + c] - m) * inv * g1[c] + b1[c];
        }
    }
    __syncthreads();

    int ty = tid >> 4, tx = tid & 15;
    int r0 = ty * 4, c0 = tx * 4;
    const float* bias[3] = { bq, bk, bv };

    for (int mmat = 0; mmat < 3; mmat++) {
        const float* W = ws + mmat * 4096;
        float acc[4][4] = {};
        for (int k = 0; k < 64; k += 4) {
            float xr[4][4];
#pragma unroll
            for (int i = 0; i < 4; i++) {
                float4 t = *(const float4*)&xs[(r0 + i) * 68 + k];
                xr[i][0] = t.x; xr[i][1] = t.y; xr[i][2] = t.z; xr[i][3] = t.w;
            }
#pragma unroll
            for (int kk = 0; kk < 4; kk++) {
                float4 w = *(const float4*)&W[(k + kk) * 64 + c0];
#pragma unroll
                for (int i = 0; i < 4; i++) {
                    acc[i][0] += xr[i][kk] * w.x;
                    acc[i][1] += xr[i][kk] * w.y;
                    acc[i][2] += xr[i][kk] * w.z;
                    acc[i][3] += xr[i][kk] * w.w;
                }
            }
        }
        const float* bb = bias[mmat];
#pragma unroll
        for (int i = 0; i < 4; i++) {
            float4 o;
            o.x = acc[i][0] + bb[c0 + 0];
            o.y = acc[i][1] + bb[c0 + 1];
            o.z = acc[i][2] + bb[c0 + 2];
            o.w = acc[i][3] + bb[c0 + 3];
            if (mmat == 0) {
                *(float4*)&g_q[(size_t)(base + r0 + i) * 64 + c0] = o;
            } else if (mmat == 1) {
                *(float4*)&kt[(r0 + i) * 68 + c0] = o;
            } else {
                *(float4*)&vt[(r0 + i) * 68 + c0] = o;
            }
        }
    }
    __syncthreads();

    // Per-head DxD rotations: out[c] = sum_d in[h*16+d] * R[h,d,c]
    int h = c0 >> 4;
    int hb = h << 4;
    int cc = c0 & 15;
    {
        float acc[4][4] = {};
#pragma unroll
        for (int d = 0; d < 16; d++) {
            float4 w = *(const float4*)&ew[h * 256 + d * 16 + cc];
#pragma unroll
            for (int i = 0; i < 4; i++) {
                float kv = kt[(r0 + i) * 68 + hb + d];
                acc[i][0] += kv * w.x;
                acc[i][1] += kv * w.y;
                acc[i][2] += kv * w.z;
                acc[i][3] += kv * w.w;
            }
        }
#pragma unroll
        for (int i = 0; i < 4; i++) {
            float4 o; o.x = acc[i][0]; o.y = acc[i][1]; o.z = acc[i][2]; o.w = acc[i][3];
            *(float4*)&g_k[(size_t)(base + r0 + i) * 64 + c0] = o;
        }
    }
    {
        float acc[4][4] = {};
#pragma unroll
        for (int d = 0; d < 16; d++) {
            float4 w = *(const float4*)&mw[h * 256 + d * 16 + cc];
#pragma unroll
            for (int i = 0; i < 4; i++) {
                float vv = vt[(r0 + i) * 68 + hb + d];
                acc[i][0] += vv * w.x;
                acc[i][1] += vv * w.y;
                acc[i][2] += vv * w.z;
                acc[i][3] += vv * w.w;
            }
        }
#pragma unroll
        for (int i = 0; i < 4; i++) {
            float4 o; o.x = acc[i][0]; o.y = acc[i][1]; o.z = acc[i][2]; o.w = acc[i][3];
            *(float4*)&g_v[(size_t)(base + r0 + i) * 64 + c0] = o;
        }
    }
}

// ---------------- edge LN + We projection (unchanged) ----------------
__global__ void k_edge_proj(const float* __restrict__ ea,
                            const float* __restrict__ g1, const float* __restrict__ b1,
                            const float* __restrict__ We, const float* __restrict__ be) {
    extern __shared__ float sm[];
    float* xs = sm;             // 64*68
    float* ws = sm + 64 * 68;   // 4096
    int tid = threadIdx.x;
    int base = blockIdx.x * 64;

    for (int i = tid; i < 4096; i += 256) {
        xs[(i >> 6) * 68 + (i & 63)] = ea[(size_t)base * 64 + i];
        ws[i] = We[i];
    }
    __syncthreads();

    {
        int row = tid >> 2, qq = tid & 3;
        float s = 0.f, s2 = 0.f;
#pragma unroll
        for (int j = 0; j < 16; j++) {
            float v = xs[row * 68 + qq * 16 + j];
            s += v; s2 += v * v;
        }
        s += __shfl_xor_sync(0xffffffffu, s, 1);
        s2 += __shfl_xor_sync(0xffffffffu, s2, 1);
        s += __shfl_xor_sync(0xffffffffu, s, 2);
        s2 += __shfl_xor_sync(0xffffffffu, s2, 2);
        float m = s * (1.f / 64.f);
        float var = s2 * (1.f / 64.f) - m * m;
        float inv = rsqrtf(var + 1e-5f);
#pragma unroll
        for (int j = 0; j < 16; j++) {
            int c = qq * 16 + j;
            xs[row * 68 + c] = (xs[row * 68 + c] - m) * inv * g1[c] + b1[c];
        }
    }
    __syncthreads();

    int ty = tid >> 4, tx = tid & 15;
    int r0 = ty * 4, c0 = tx * 4;
    float acc[4][4] = {};
    for (int k = 0; k < 64; k += 4) {
        float xr[4][4];
#pragma unroll
        for (int i = 0; i < 4; i++) {
            float4 t = *(const float4*)&xs[(r0 + i) * 68 + k];
            xr[i][0] = t.x; xr[i][1] = t.y; xr[i][2] = t.z; xr[i][3] = t.w;
        }
#pragma unroll
        for (int kk = 0; kk < 4; kk++) {
            float4 w = *(const float4*)&ws[(k + kk) * 64 + c0];
#pragma unroll
            for (int i = 0; i < 4; i++) {
                acc[i][0] += xr[i][kk] * w.x;
                acc[i][1] += xr[i][kk] * w.y;
                acc[i][2] += xr[i][kk] * w.z;
                acc[i][3] += xr[i][kk] * w.w;
            }
        }
    }
#pragma unroll
    for (int i = 0; i < 4; i++) {
        float4 o;
        o.x = acc[i][0] + be[c0 + 0];
        o.y = acc[i][1] + be[c0 + 1];
        o.z = acc[i][2] + be[c0 + 2];
        o.w = acc[i][3] + be[c0 + 3];
        *(float4*)&g_e[(size_t)(base + r0 + i) * 64 + c0] = o;
    }
}

// ---------------- scores: q . (k_rot * e), 2 edges per warp -----------------
// lane L (0..15) of each half-warp owns cols 4L..4L+3 (head h = L>>2).
__global__ void k_score(const int* __restrict__ eidx,
                        const float* __restrict__ attn_bi) {
    __shared__ float bi[4];
    int tid = threadIdx.x;
    if (tid < 4) bi[tid] = attn_bi[tid * 2];   // attn_bi[:,0]
    __syncthreads();

    int lane = tid & 31;
    int sub = lane >> 4, L = lane & 15;
    int e = blockIdx.x * 16 + (tid >> 5) * 2 + sub;
    int src = eidx[e];
    int dst = eidx[EE + e];

    float4 kr = *(const float4*)&g_k[(size_t)src * 64 + L * 4];
    float4 ee = *(const float4*)&g_e[(size_t)e * 64 + L * 4];
    float4 qq = *(const float4*)&g_q[(size_t)dst * 64 + L * 4];

    float p = qq.x * (kr.x * ee.x) + qq.y * (kr.y * ee.y)
            + qq.z * (kr.z * ee.z) + qq.w * (kr.w * ee.w);
    p += __shfl_xor_sync(0xffffffffu, p, 1);
    p += __shfl_xor_sync(0xffffffffu, p, 2);

    if ((L & 3) == 0) {
        int h = L >> 2;
        float s = p * 0.25f + bi[h];           // scale = 1/sqrt(16)
        g_w[e * 4 + h] = s;
        atomicMax(&g_smax[dst * 4 + h], enc_f(s));
    }
}

// ---------------- segment softmax: exp + segment sum ----------------
__global__ void k_norm(const int* __restrict__ eidx) {
    int i = blockIdx.x * blockDim.x + threadIdx.x;   // E*H
    int e = i >> 2, h = i & 3;
    int dst = eidx[EE + e];
    float w = expf(g_w[i] - dec_f(g_smax[dst * 4 + h]));
    g_w[i] = w;
    atomicAdd(&g_ssum[dst * 4 + h], w);
}

// ---------------- scatter: alpha * v_rot, vector red.v4 atomics -------------
__global__ void k_scatter(const int* __restrict__ eidx) {
    int tid = threadIdx.x;
    int lane = tid & 31;
    int sub = lane >> 4, L = lane & 15;
    int e = blockIdx.x * 16 + (tid >> 5) * 2 + sub;
    int src = eidx[e];
    int dst = eidx[EE + e];
    int h = L >> 2;

    float4 v = *(const float4*)&g_v[(size_t)src * 64 + L * 4];
    float al = g_w[e * 4 + h] / (g_ssum[dst * 4 + h] + 1e-16f);
    float* p = &g_attn[(size_t)dst * 64 + L * 4];
    asm volatile("red.global.add.v4.f32 [%0], {%1, %2, %3, %4};"
                 :: "l"(p), "f"(al * v.x), "f"(al * v.y),
                    "f"(al * v.z), "f"(al * v.w)
                 : "memory");
}

// ---------------- epilogue: Wo + gated residual + LN + FFN (unchanged) ------
__global__ void k_epi(const float* __restrict__ x,
                      const float* __restrict__ Wo, const float* __restrict__ bo,
                      const float* __restrict__ skip,
                      const float* __restrict__ g2, const float* __restrict__ b2,
                      const float* __restrict__ W1, const float* __restrict__ b1f,
                      const float* __restrict__ W2, const float* __restrict__ b2f,
                      float* __restrict__ out) {
    extern __shared__ float sm[];
    float* s_a  = sm;               // 64*68
    float* s_h  = s_a + 4352;       // 4352
    float* s_u  = s_h + 4352;       // 64*132 = 8448

    int tid = threadIdx.x;
    int base = blockIdx.x * 64;

    for (int i = tid; i < 4096; i += 256) {
        s_a[(i >> 6) * 68 + (i & 63)] = g_attn[(size_t)base * 64 + i];
    }
    __syncthreads();

    int ty = tid >> 4, tx = tid & 15;
    int r0 = ty * 4, c0 = tx * 4;
    float gsig = 1.f / (1.f + expf(-skip[0]));
    float hreg[4][4];

    {
        float acc[4][4] = {};
        for (int k = 0; k < 64; k += 4) {
            float xr[4][4];
#pragma unroll
            for (int i = 0; i < 4; i++) {
                float4 t = *(const float4*)&s_a[(r0 + i) * 68 + k];
                xr[i][0] = t.x; xr[i][1] = t.y; xr[i][2] = t.z; xr[i][3] = t.w;
            }
#pragma unroll
            for (int kk = 0; kk < 4; kk++) {
                float4 w = __ldg((const float4*)&Wo[(k + kk) * 64 + c0]);
#pragma unroll
                for (int i = 0; i < 4; i++) {
                    acc[i][0] += xr[i][kk] * w.x;
                    acc[i][1] += xr[i][kk] * w.y;
                    acc[i][2] += xr[i][kk] * w.z;
                    acc[i][3] += xr[i][kk] * w.w;
                }
            }
        }
#pragma unroll
        for (int i = 0; i < 4; i++) {
            float4 xv = *(const float4*)&x[(size_t)(base + r0 + i) * 64 + c0];
            hreg[i][0] = gsig * (acc[i][0] + bo[c0 + 0]) + (1.f - gsig) * xv.x;
            hreg[i][1] = gsig * (acc[i][1] + bo[c0 + 1]) + (1.f - gsig) * xv.y;
            hreg[i][2] = gsig * (acc[i][2] + bo[c0 + 2]) + (1.f - gsig) * xv.z;
            hreg[i][3] = gsig * (acc[i][3] + bo[c0 + 3]) + (1.f - gsig) * xv.w;
            float4 hv;
            hv.x = hreg[i][0]; hv.y = hreg[i][1]; hv.z = hreg[i][2]; hv.w = hreg[i][3];
            *(float4*)&s_h[(r0 + i) * 68 + c0] = hv;
        }
    }
    __syncthreads();

    {
        int row = tid >> 2, qq = tid & 3;
        float s = 0.f, s2 = 0.f;
#pragma unroll
        for (int j = 0; j < 16; j++) {
            float v = s_h[row * 68 + qq * 16 + j];
            s += v; s2 += v * v;
        }
        s += __shfl_xor_sync(0xffffffffu, s, 1);
        s2 += __shfl_xor_sync(0xffffffffu, s2, 1);
        s += __shfl_xor_sync(0xffffffffu, s, 2);
        s2 += __shfl_xor_sync(0xffffffffu, s2, 2);
        float m = s * (1.f / 64.f);
        float var = s2 * (1.f / 64.f) - m * m;
        float inv = rsqrtf(var + 1e-5f);
#pragma unroll
        for (int j = 0; j < 16; j++) {
            int cc = qq * 16 + j;
            s_a[row * 68 + cc] = (s_h[row * 68 + cc] - m) * inv * g2[cc] + b2[cc];
        }
    }
    __syncthreads();

    {
        float acc[4][8] = {};
        for (int k = 0; k < 64; k += 4) {
            float xr[4][4];
#pragma unroll
            for (int i = 0; i < 4; i++) {
                float4 t = *(const float4*)&s_a[(r0 + i) * 68 + k];
                xr[i][0] = t.x; xr[i][1] = t.y; xr[i][2] = t.z; xr[i][3] = t.w;
            }
#pragma unroll
            for (int kk = 0; kk < 4; kk++) {
                float4 wa = __ldg((const float4*)&W1[(k + kk) * 128 + tx * 8]);
                float4 wb = __ldg((const float4*)&W1[(k + kk) * 128 + tx * 8 + 4]);
#pragma unroll
                for (int i = 0; i < 4; i++) {
                    acc[i][0] += xr[i][kk] * wa.x;
                    acc[i][1] += xr[i][kk] * wa.y;
                    acc[i][2] += xr[i][kk] * wa.z;
                    acc[i][3] += xr[i][kk] * wa.w;
                    acc[i][4] += xr[i][kk] * wb.x;
                    acc[i][5] += xr[i][kk] * wb.y;
                    acc[i][6] += xr[i][kk] * wb.z;
                    acc[i][7] += xr[i][kk] * wb.w;
                }
            }
        }
        int u0 = tx * 8;
#pragma unroll
        for (int i = 0; i < 4; i++) {
#pragma unroll
            for (int j = 0; j < 8; j++) {
                float uu = acc[i][j] + b1f[u0 + j];
                s_u[(r0 + i) * 132 + u0 + j] = fmaxf(uu, 0.f);
            }
        }
    }
    __syncthreads();

    {
        float acc[4][4] = {};
        for (int k = 0; k < 128; k += 4) {
            float xr[4][4];
#pragma unroll
            for (int i = 0; i < 4; i++) {
                float4 t = *(const float4*)&s_u[(r0 + i) * 132 + k];
                xr[i][0] = t.x; xr[i][1] = t.y; xr[i][2] = t.z; xr[i][3] = t.w;
            }
#pragma unroll
            for (int kk = 0; kk < 4; kk++) {
                float4 w = __ldg((const float4*)&W2[(k + kk) * 64 + c0]);
#pragma unroll
                for (int i = 0; i < 4; i++) {
                    acc[i][0] += xr[i][kk] * w.x;
                    acc[i][1] += xr[i][kk] * w.y;
                    acc[i][2] += xr[i][kk] * w.z;
                    acc[i][3] += xr[i][kk] * w.w;
                }
            }
        }
#pragma unroll
        for (int i = 0; i < 4; i++) {
            float4 o;
            o.x = hreg[i][0] + acc[i][0] + b2f[c0 + 0];
            o.y = hreg[i][1] + acc[i][1] + b2f[c0 + 1];
            o.z = hreg[i][2] + acc[i][2] + b2f[c0 + 2];
            o.w = hreg[i][3] + acc[i][3] + b2f[c0 + 3];
            *(float4*)&out[(size_t)(base + r0 + i) * 64 + c0] = o;
        }
    }
}

// ---------------- host launcher ----------------
extern "C" void kernel_launch(void* const* d_in, const int* in_sizes, int n_in,
                              void* d_out, int out_size) {
    const float* x      = (const float*)d_in[0];
    const int*   eidx   = (const int*)d_in[1];
    const float* ea     = (const float*)d_in[2];
    const float* Wq     = (const float*)d_in[3];
    const float* bq     = (const float*)d_in[4];
    const float* Wk     = (const float*)d_in[5];
    const float* bk     = (const float*)d_in[6];
    const float* Wv     = (const float*)d_in[7];
    const float* bv     = (const float*)d_in[8];
    const float* We     = (const float*)d_in[9];
    const float* be     = (const float*)d_in[10];
    const float* Wo     = (const float*)d_in[11];
    const float* bo     = (const float*)d_in[12];
    const float* edge_w = (const float*)d_in[13];
    const float* msg_w  = (const float*)d_in[14];
    const float* skip   = (const float*)d_in[15];
    const float* ln1_g  = (const float*)d_in[16];
    const float* ln1_b  = (const float*)d_in[17];
    const float* lne_g  = (const float*)d_in[18];
    const float* lne_b  = (const float*)d_in[19];
    const float* ln2_g  = (const float*)d_in[20];
    const float* ln2_b  = (const float*)d_in[21];
    const float* W1     = (const float*)d_in[22];
    const float* b1     = (const float*)d_in[23];
    const float* W2     = (const float*)d_in[24];
    const float* b2     = (const float*)d_in[25];
    const float* attn_bi= (const float*)d_in[26];
    float* out = (float*)d_out;

    cudaFuncSetAttribute(k_node_qkv, cudaFuncAttributeMaxDynamicSharedMemorySize, 112640);
    cudaFuncSetAttribute(k_epi,      cudaFuncAttributeMaxDynamicSharedMemorySize, 69632);

    k_init<<<(NN * DHH + 255) / 256, 256>>>();
    k_node_qkv<<<NN / 64, 256, 109568>>>(x, ln1_g, ln1_b, Wq, bq, Wk, bk, Wv, bv,
                                         edge_w, msg_w);
    k_edge_proj<<<EE / 64, 256, 33792>>>(ea, lne_g, lne_b, We, be);
    k_score<<<EE / 16, 256>>>(eidx, attn_bi);
    k_norm<<<(EE * HH) / 256, 256>>>(eidx);
    k_scatter<<<EE / 16, 256>>>(eidx);
    k_epi<<<NN / 64, 256, 68608>>>(x, Wo, bo, skip, ln2_g, ln2_b, W1, b1, W2, b2, out);
}